// round 13
// baseline (speedup 1.0000x reference)
#include <cuda_runtime.h>
#include <cstdint>

#define MARGIN 0.3f
#define EPSV   1e-6f

#define MAX_B 8192
#define UINF  0xFFFFFFFFu

__device__ float2 g_part[MAX_B/16 + 1];  // per-block {loss_sum, valid_cnt}

__device__ __forceinline__ int read_label(const void* lab, int i, int is64) {
    if (is64) return (int)((const long long*)lab)[i];
    return ((const int*)lab)[i];
}

// ================================================================ kernel A
// Warp per anchor. Pos/neg found by per-warp ballot scan over labels
// (L1-hot), fully hidden behind the anchor's in-flight DRAM loads.
__global__ void k_dist(const float* __restrict__ features,
                       const void* __restrict__ labels, int B, int D) {
    __shared__ float s_loss[16];
    __shared__ int   s_val[16];
    int wib  = threadIdx.x >> 5;
    int warp = blockIdx.x * (blockDim.x >> 5) + wib;
    int lane = threadIdx.x & 31;

    // dtype detect (block-local, globally consistent): odd 32-bit words < B
    // are high halves of int64 labels (zero when labels < 2^32) or
    // independent int32 labels (never all zero). Labels are L2/L1-hot.
    const int* w = (const int*)labels;
    int any = 0;
    for (int i = 2 * (int)threadIdx.x + 1; i < B; i += 2 * (int)blockDim.x)
        any |= w[i];
    int is64 = (__syncthreads_or(any) == 0);

    float my_loss = 0.0f;
    int   my_val  = 0;

    if (warp < B) {
        const float4* __restrict__ A = (const float4*)(features + (size_t)warp * D);

        // 1) launch anchor loads first — scan hides behind them
        float4 a[8];
        if (D == 1024) {
            #pragma unroll
            for (int k = 0; k < 8; k++) a[k] = __ldcs(&A[lane + 32 * k]);
        }

        // 2) resolve pos/neg by ballot scan (early-exit; labels L1-hot)
        int lab_i = read_label(labels, warp, is64);
        int l0    = read_label(labels, 0, is64);

        unsigned p = UINF;
        for (int c = 0; c < B; c += 32) {
            int j = c + lane;
            int lj = (j < B) ? read_label(labels, j, is64) : ~lab_i;
            unsigned m = __ballot_sync(0xffffffffu, lj == lab_i && j != warp && j < B);
            if (m) { p = c + __ffs(m) - 1; break; }
        }
        unsigned n = UINF;
        if (lab_i != l0) {
            n = 0;
        } else {
            for (int c = 0; c < B; c += 32) {
                int j = c + lane;
                int lj = (j < B) ? read_label(labels, j, is64) : l0;
                unsigned m = __ballot_sync(0xffffffffu, lj != l0 && j < B);
                if (m) { n = c + __ffs(m) - 1; break; }
            }
        }

        if (p != UINF && n != UINF) {
            const float4* __restrict__ P = (const float4*)(features + (size_t)p * D);
            const float4* __restrict__ N = (const float4*)(features + (size_t)n * D);
            float sap = 0.0f, san = 0.0f;

            if (D == 1024) {
                // 3) stream P/N with one-stage prefetch against landed anchors
                float4 pp = P[lane];
                float4 nn = N[lane];
                #pragma unroll
                for (int k = 1; k <= 8; k++) {
                    float4 p2, n2;
                    if (k < 8) {
                        p2 = P[lane + 32 * k];
                        n2 = N[lane + 32 * k];
                    }
                    float d;
                    d = a[k-1].x - pp.x + EPSV; sap = fmaf(d, d, sap);
                    d = a[k-1].y - pp.y + EPSV; sap = fmaf(d, d, sap);
                    d = a[k-1].z - pp.z + EPSV; sap = fmaf(d, d, sap);
                    d = a[k-1].w - pp.w + EPSV; sap = fmaf(d, d, sap);
                    d = a[k-1].x - nn.x + EPSV; san = fmaf(d, d, san);
                    d = a[k-1].y - nn.y + EPSV; san = fmaf(d, d, san);
                    d = a[k-1].z - nn.z + EPSV; san = fmaf(d, d, san);
                    d = a[k-1].w - nn.w + EPSV; san = fmaf(d, d, san);
                    pp = p2; nn = n2;
                }
            } else {
                int nv = D >> 2;
                for (int k = lane; k < nv; k += 32) {
                    float4 av = A[k], pp = P[k], nn = N[k];
                    float d;
                    d = av.x - pp.x + EPSV; sap = fmaf(d, d, sap);
                    d = av.y - pp.y + EPSV; sap = fmaf(d, d, sap);
                    d = av.z - pp.z + EPSV; sap = fmaf(d, d, sap);
                    d = av.w - pp.w + EPSV; sap = fmaf(d, d, sap);
                    d = av.x - nn.x + EPSV; san = fmaf(d, d, san);
                    d = av.y - nn.y + EPSV; san = fmaf(d, d, san);
                    d = av.z - nn.z + EPSV; san = fmaf(d, d, san);
                    d = av.w - nn.w + EPSV; san = fmaf(d, d, san);
                }
            }
            #pragma unroll
            for (int off = 16; off > 0; off >>= 1) {
                sap += __shfl_down_sync(0xffffffffu, sap, off);
                san += __shfl_down_sync(0xffffffffu, san, off);
            }
            my_loss = fmaxf(sqrtf(sap) - sqrtf(san) + MARGIN, 0.0f);
            my_val  = 1;
        }
    }

    // block-partial reduction (fixed order -> deterministic)
    if (lane == 0) { s_loss[wib] = my_loss; s_val[wib] = my_val; }
    __syncthreads();
    if (threadIdx.x == 0) {
        float sum = 0.0f; int cnt = 0;
        #pragma unroll
        for (int j = 0; j < 16; j++) { sum += s_loss[j]; cnt += s_val[j]; }
        g_part[blockIdx.x] = make_float2(sum, (float)cnt);
    }
}

// ================================================================ kernel B
// Deterministic single-block reduction over block partials.
__global__ void k_reduce(float* __restrict__ out, int npart) {
    __shared__ float s_sum[512];
    __shared__ float s_cnt[512];
    int t = threadIdx.x;
    float sum = 0.0f, cnt = 0.0f;
    for (int i = t; i < npart; i += blockDim.x) {
        float2 v = g_part[i];
        sum += v.x; cnt += v.y;
    }
    s_sum[t] = sum;
    s_cnt[t] = cnt;
    __syncthreads();
    for (int off = (int)blockDim.x >> 1; off > 0; off >>= 1) {
        if (t < off) {
            s_sum[t] += s_sum[t + off];
            s_cnt[t] += s_cnt[t + off];
        }
        __syncthreads();
    }
    if (t == 0)
        out[0] = (s_cnt[0] > 0.0f) ? (s_sum[0] / s_cnt[0]) : 0.0f;
}

// ================================================================ launch
extern "C" void kernel_launch(void* const* d_in, const int* in_sizes, int n_in,
                              void* d_out, int out_size) {
    int i_feat = (in_sizes[0] >= in_sizes[1]) ? 0 : 1;
    int i_lab  = 1 - i_feat;
    const float* features = (const float*)d_in[i_feat];
    const void*  labels   = d_in[i_lab];
    int B = in_sizes[i_lab];
    int D = in_sizes[i_feat] / B;

    int nblk = (B + 15) / 16;       // 16 anchors per 512-thread block
    k_dist  <<<nblk, 512>>>(features, labels, B, D);
    k_reduce<<<1, 512>>>((float*)d_out, nblk);
}

// round 14
// speedup vs baseline: 1.5660x; 1.5660x over previous
#include <cuda_runtime.h>
#include <cstdint>

#define MARGIN 0.3f
#define EPSV   1e-6f

#define MAX_B  8192
#define MAX_L  1024
#define NSLOT  8
#define UINF   0xFFFFFFFFu

__device__ int2     g_tabs[NSLOT][MAX_L];   // per-slot {m1,m2} per label (no atomics)
__device__ unsigned g_diffs[NSLOT];         // per-slot first-differing index
__device__ int      g_lab32[MAX_B];         // decoded int32 labels
__device__ float2   g_part[MAX_B/8 + 1];    // per-block {loss_sum, valid_cnt}

// ================================================================ kernel A
// Fixed grid of NSLOT blocks. Per-block smem two-min tables over a slice,
// written to a private global slot — no global atomics, no memset needed.
__global__ void k_occ_part(const void* __restrict__ labels, int B) {
    __shared__ unsigned s_m1[MAX_L];
    __shared__ unsigned s_m2[MAX_L];
    __shared__ unsigned s_diff;
    int t = threadIdx.x;
    int nt = blockDim.x;
    int lane = t & 31;

    for (int j = t; j < MAX_L; j += nt) { s_m1[j] = UINF; s_m2[j] = UINF; }
    if (t == 0) s_diff = UINF;

    // dtype detect (full range, redundant per block -> globally consistent).
    // Odd 32-bit words < B are high halves of int64 labels (zero when
    // labels < 2^32) or independent int32 labels (never all zero).
    const int* w = (const int*)labels;
    int any = 0;
    for (int i = 2 * t + 1; i < B; i += 2 * nt) any |= w[i];
    int is64 = (__syncthreads_or(any) == 0);   // also orders smem init

    int l0 = is64 ? (int)((const long long*)labels)[0] : w[0];

    int slice = (B + NSLOT - 1) / NSLOT;
    int base  = blockIdx.x * slice;
    int end   = min(base + slice, B);

    unsigned cand = UINF;
    for (int i = base + t; i < end; i += nt) {
        int lab = is64 ? (int)((const long long*)labels)[i] : w[i];
        g_lab32[i] = lab;
        if ((unsigned)lab < MAX_L) {
            // loser-feeds-m2 two-min (validated R10/R11)
            unsigned old = atomicMin(&s_m1[lab], (unsigned)i);
            if (old != UINF) atomicMin(&s_m2[lab], ((unsigned)i < old) ? old : (unsigned)i);
        }
        if (lab != l0 && (unsigned)i < cand) cand = (unsigned)i;
    }
    #pragma unroll
    for (int off = 16; off > 0; off >>= 1)
        cand = min(cand, __shfl_down_sync(0xffffffffu, cand, off));
    if (lane == 0 && cand != UINF) atomicMin(&s_diff, cand);
    __syncthreads();

    // publish local table to this block's private slot (coalesced, non-atomic)
    for (int j = t; j < MAX_L; j += nt)
        g_tabs[blockIdx.x][j] = make_int2((int)s_m1[j], (int)s_m2[j]);
    if (t == 0) g_diffs[blockIdx.x] = s_diff;
}

// ================================================================ kernel B
// TWO warps per anchor (half-D each) -> halved per-warp serial load chain.
// Pos/neg resolved by register-merging the NSLOT table slots (uniform loads).
__global__ void k_dist(const float* __restrict__ features, int B, int D) {
    __shared__ float2 s_ap[16];     // per-warp partial {sap, san}
    __shared__ float  s_loss[8];
    __shared__ int    s_val[8];
    int wib    = threadIdx.x >> 5;              // 0..15
    int gwarp  = blockIdx.x * 16 + wib;
    int anchor = gwarp >> 1;
    int half   = gwarp & 1;
    int lane   = threadIdx.x & 31;

    float sap = 0.0f, san = 0.0f;
    unsigned p = UINF, n = UINF;

    if (anchor < B) {
        const float4* __restrict__ A = (const float4*)(features + (size_t)anchor * D);

        // 1) issue this half's anchor loads first (DRAM, longest latency)
        float4 a[4];
        if (D == 1024) {
            #pragma unroll
            for (int j = 0; j < 4; j++)
                a[j] = __ldcs(&A[lane + 32 * (half * 4 + j)]);
        }

        // 2) resolve pos/neg while anchors are in flight
        int lab = g_lab32[anchor];
        if ((unsigned)lab < MAX_L) {
            unsigned m1 = UINF, m2 = UINF;
            #pragma unroll
            for (int s = 0; s < NSLOT; s++) {
                int2 e = g_tabs[s][lab];
                unsigned v = (unsigned)e.x;
                if (v < m1) { m2 = m1; m1 = v; } else if (v < m2) { m2 = v; }
                v = (unsigned)e.y;
                if (v < m1) { m2 = m1; m1 = v; } else if (v < m2) { m2 = v; }
            }
            p = (m1 == (unsigned)anchor) ? m2 : m1;
            if (lab != g_lab32[0]) {
                n = 0;
            } else {
                unsigned dm = UINF;
                #pragma unroll
                for (int s = 0; s < NSLOT; s++) dm = min(dm, g_diffs[s]);
                n = dm;
            }
        }

        if (p != UINF && n != UINF) {
            const float4* __restrict__ P = (const float4*)(features + (size_t)p * D);
            const float4* __restrict__ N = (const float4*)(features + (size_t)n * D);

            if (D == 1024) {
                int k0 = half * 4;
                float4 pp = P[lane + 32 * k0];
                float4 nn = N[lane + 32 * k0];
                #pragma unroll
                for (int j = 1; j <= 4; j++) {
                    float4 p2, n2;
                    if (j < 4) {
                        p2 = P[lane + 32 * (k0 + j)];
                        n2 = N[lane + 32 * (k0 + j)];
                    }
                    float d;
                    d = a[j-1].x - pp.x + EPSV; sap = fmaf(d, d, sap);
                    d = a[j-1].y - pp.y + EPSV; sap = fmaf(d, d, sap);
                    d = a[j-1].z - pp.z + EPSV; sap = fmaf(d, d, sap);
                    d = a[j-1].w - pp.w + EPSV; sap = fmaf(d, d, sap);
                    d = a[j-1].x - nn.x + EPSV; san = fmaf(d, d, san);
                    d = a[j-1].y - nn.y + EPSV; san = fmaf(d, d, san);
                    d = a[j-1].z - nn.z + EPSV; san = fmaf(d, d, san);
                    d = a[j-1].w - nn.w + EPSV; san = fmaf(d, d, san);
                    pp = p2; nn = n2;
                }
            } else {
                int nv  = D >> 2;
                int nvh = (nv + 1) >> 1;
                int kb  = half * nvh;
                int ke  = min(kb + nvh, nv);
                for (int k = kb + lane; k < ke * 1; k += 32) { }  // (unused guard)
                for (int k = kb; k < ke; k++) {
                    // one float4 per iteration per lane-strided index
                    int idx = k;            // element-block index
                    // stride lanes across the float4 index space
                    // (simple: lane handles idx when (idx % 32)==lane)
                    if ((idx & 31) == lane) {
                        float4 av = A[idx], pp = P[idx], nn = N[idx];
                        float d;
                        d = av.x - pp.x + EPSV; sap = fmaf(d, d, sap);
                        d = av.y - pp.y + EPSV; sap = fmaf(d, d, sap);
                        d = av.z - pp.z + EPSV; sap = fmaf(d, d, sap);
                        d = av.w - pp.w + EPSV; sap = fmaf(d, d, sap);
                        d = av.x - nn.x + EPSV; san = fmaf(d, d, san);
                        d = av.y - nn.y + EPSV; san = fmaf(d, d, san);
                        d = av.z - nn.z + EPSV; san = fmaf(d, d, san);
                        d = av.w - nn.w + EPSV; san = fmaf(d, d, san);
                    }
                }
            }
        }
    }

    // intra-warp reduce
    #pragma unroll
    for (int off = 16; off > 0; off >>= 1) {
        sap += __shfl_down_sync(0xffffffffu, sap, off);
        san += __shfl_down_sync(0xffffffffu, san, off);
    }
    if (lane == 0) s_ap[wib] = make_float2(sap, san);
    __syncthreads();

    // pair-combine (even warp of each pair), then per-anchor loss
    if ((wib & 1) == 0 && lane == 0) {
        int aidx = blockIdx.x * 8 + (wib >> 1);
        float loss = 0.0f; int val = 0;
        if (aidx < B) {
            int lab = g_lab32[aidx];
            // validity re-derived cheaply: p/n existence == both sums meaningful.
            // Recompute validity from table (uniform, L1-hot).
            unsigned m1 = UINF, m2 = UINF;
            if ((unsigned)lab < MAX_L) {
                #pragma unroll
                for (int s = 0; s < NSLOT; s++) {
                    int2 e = g_tabs[s][lab];
                    unsigned v = (unsigned)e.x;
                    if (v < m1) { m2 = m1; m1 = v; } else if (v < m2) { m2 = v; }
                    v = (unsigned)e.y;
                    if (v < m1) { m2 = m1; m1 = v; } else if (v < m2) { m2 = v; }
                }
            }
            unsigned pp = (m1 == (unsigned)aidx) ? m2 : m1;
            unsigned nn;
            if ((unsigned)lab < MAX_L && lab != g_lab32[0]) {
                nn = 0;
            } else {
                unsigned dm = UINF;
                #pragma unroll
                for (int s = 0; s < NSLOT; s++) dm = min(dm, g_diffs[s]);
                nn = ((unsigned)lab < MAX_L) ? dm : UINF;
            }
            if (pp != UINF && nn != UINF) {
                float2 u = s_ap[wib];
                float2 v2 = s_ap[wib + 1];
                float dap = sqrtf(u.x + v2.x);
                float dan = sqrtf(u.y + v2.y);
                loss = fmaxf(dap - dan + MARGIN, 0.0f);
                val  = 1;
            }
        }
        s_loss[wib >> 1] = loss;
        s_val[wib >> 1]  = val;
    }
    __syncthreads();
    if (threadIdx.x == 0) {
        float sum = 0.0f; int cnt = 0;
        #pragma unroll
        for (int j = 0; j < 8; j++) { sum += s_loss[j]; cnt += s_val[j]; }
        g_part[blockIdx.x] = make_float2(sum, (float)cnt);
    }
}

// ================================================================ kernel C
// Deterministic single-block reduction over block partials.
__global__ void k_reduce(float* __restrict__ out, int npart) {
    __shared__ float s_sum[512];
    __shared__ float s_cnt[512];
    int t = threadIdx.x;
    float sum = 0.0f, cnt = 0.0f;
    for (int i = t; i < npart; i += blockDim.x) {
        float2 v = g_part[i];
        sum += v.x; cnt += v.y;
    }
    s_sum[t] = sum;
    s_cnt[t] = cnt;
    __syncthreads();
    for (int off = (int)blockDim.x >> 1; off > 0; off >>= 1) {
        if (t < off) {
            s_sum[t] += s_sum[t + off];
            s_cnt[t] += s_cnt[t + off];
        }
        __syncthreads();
    }
    if (t == 0)
        out[0] = (s_cnt[0] > 0.0f) ? (s_sum[0] / s_cnt[0]) : 0.0f;
}

// ================================================================ launch
extern "C" void kernel_launch(void* const* d_in, const int* in_sizes, int n_in,
                              void* d_out, int out_size) {
    int i_feat = (in_sizes[0] >= in_sizes[1]) ? 0 : 1;
    int i_lab  = 1 - i_feat;
    const float* features = (const float*)d_in[i_feat];
    const void*  labels   = d_in[i_lab];
    int B = in_sizes[i_lab];
    int D = in_sizes[i_feat] / B;

    int nblk = (B + 7) / 8;         // 8 anchors (16 warps) per 512-thread block
    k_occ_part<<<NSLOT, 1024>>>(labels, B);
    k_dist    <<<nblk, 512>>>(features, B, D);
    k_reduce  <<<1, 512>>>((float*)d_out, nblk);
}

// round 15
// speedup vs baseline: 1.9233x; 1.2282x over previous
#include <cuda_runtime.h>
#include <cstdint>

#define MARGIN 0.3f
#define EPSV   1e-6f

#define MAX_B  8192
#define MAX_L  1024
#define NSLOT  8
#define UINF   0xFFFFFFFFu

__device__ int2     g_tabs[NSLOT][MAX_L];   // per-slot {m1,m2} per label (no atomics)
__device__ unsigned g_diffs[NSLOT];         // per-slot first-differing index
__device__ int      g_lab32[MAX_B];         // decoded int32 labels
__device__ float2   g_part[MAX_B/16 + 1];   // per-block {loss_sum, valid_cnt}

// ================================================================ kernel A
// Fixed grid of NSLOT blocks. Per-block smem two-min tables over a slice,
// published to private global slots — no memset, no global atomics.
__global__ void k_occ_part(const void* __restrict__ labels, int B) {
    __shared__ unsigned s_m1[MAX_L];
    __shared__ unsigned s_m2[MAX_L];
    __shared__ unsigned s_diff;
    int t = threadIdx.x;
    int nt = blockDim.x;
    int lane = t & 31;

    for (int j = t; j < MAX_L; j += nt) { s_m1[j] = UINF; s_m2[j] = UINF; }
    if (t == 0) s_diff = UINF;

    // dtype detect (full range, redundant per block -> globally consistent).
    // Odd 32-bit words < B are high halves of int64 labels (zero when
    // labels < 2^32) or independent int32 labels (never all zero).
    const int* w = (const int*)labels;
    int any = 0;
    for (int i = 2 * t + 1; i < B; i += 2 * nt) any |= w[i];
    int is64 = (__syncthreads_or(any) == 0);   // also orders smem init

    int l0 = is64 ? (int)((const long long*)labels)[0] : w[0];

    int slice = (B + NSLOT - 1) / NSLOT;
    int base  = blockIdx.x * slice;
    int end   = min(base + slice, B);

    unsigned cand = UINF;
    for (int i = base + t; i < end; i += nt) {
        int lab = is64 ? (int)((const long long*)labels)[i] : w[i];
        g_lab32[i] = lab;
        if ((unsigned)lab < MAX_L) {
            // loser-feeds-m2 two-min (validated R10/R11/R14)
            unsigned old = atomicMin(&s_m1[lab], (unsigned)i);
            if (old != UINF) atomicMin(&s_m2[lab], ((unsigned)i < old) ? old : (unsigned)i);
        }
        if (lab != l0 && (unsigned)i < cand) cand = (unsigned)i;
    }
    #pragma unroll
    for (int off = 16; off > 0; off >>= 1)
        cand = min(cand, __shfl_down_sync(0xffffffffu, cand, off));
    if (lane == 0 && cand != UINF) atomicMin(&s_diff, cand);
    __syncthreads();

    // publish local table to this block's private slot (coalesced, non-atomic)
    for (int j = t; j < MAX_L; j += nt)
        g_tabs[blockIdx.x][j] = make_int2((int)s_m1[j], (int)s_m2[j]);
    if (t == 0) g_diffs[blockIdx.x] = s_diff;
}

// ================================================================ kernel B
// R11 shape: warp per anchor, 24-load 2-stage pipeline. Pos/neg resolved by
// register-merging the NSLOT slots (uniform loads, hidden behind A prefetch).
__global__ void k_dist(const float* __restrict__ features, int B, int D) {
    __shared__ float s_loss[16];
    __shared__ int   s_val[16];
    int wib  = threadIdx.x >> 5;
    int warp = blockIdx.x * (blockDim.x >> 5) + wib;
    int lane = threadIdx.x & 31;

    float my_loss = 0.0f;
    int   my_val  = 0;

    if (warp < B) {
        const float4* __restrict__ A = (const float4*)(features + (size_t)warp * D);

        // 1) issue anchor loads first (DRAM, longest latency)
        float4 a0, a1;
        if (D == 1024) {
            a0 = __ldcs(&A[lane]);
            a1 = __ldcs(&A[lane + 32]);
        }

        // 2) resolve pos/neg from slot tables while anchors are in flight
        int lab = g_lab32[warp];
        unsigned p = UINF, n = UINF;
        if ((unsigned)lab < MAX_L) {
            unsigned m1 = UINF, m2 = UINF;
            #pragma unroll
            for (int s = 0; s < NSLOT; s++) {
                int2 e = g_tabs[s][lab];
                unsigned v = (unsigned)e.x;
                if (v < m1) { m2 = m1; m1 = v; } else if (v < m2) { m2 = v; }
                v = (unsigned)e.y;
                if (v < m1) { m2 = m1; m1 = v; } else if (v < m2) { m2 = v; }
            }
            p = (m1 == (unsigned)warp) ? m2 : m1;
            if (lab != g_lab32[0]) {
                n = 0;
            } else {
                unsigned dm = UINF;
                #pragma unroll
                for (int s = 0; s < NSLOT; s++) dm = min(dm, g_diffs[s]);
                n = dm;
            }
        }

        if (p != UINF && n != UINF) {
            const float4* __restrict__ P = (const float4*)(features + (size_t)p * D);
            const float4* __restrict__ N = (const float4*)(features + (size_t)n * D);
            float sap = 0.0f, san = 0.0f;

            if (D == 1024) {
                // 2-stage pipeline (R11-validated), anchors a0 pre-issued
                float4 a  = a0;
                float4 pp = P[lane];
                float4 nn = N[lane];
                #pragma unroll
                for (int k = 1; k <= 8; k++) {
                    float4 a2, p2, n2;
                    if (k < 8) {
                        a2 = (k == 1) ? a1 : __ldcs(&A[lane + 32 * k]);
                        p2 = P[lane + 32 * k];
                        n2 = N[lane + 32 * k];
                    }
                    float d;
                    d = a.x - pp.x + EPSV; sap = fmaf(d, d, sap);
                    d = a.y - pp.y + EPSV; sap = fmaf(d, d, sap);
                    d = a.z - pp.z + EPSV; sap = fmaf(d, d, sap);
                    d = a.w - pp.w + EPSV; sap = fmaf(d, d, sap);
                    d = a.x - nn.x + EPSV; san = fmaf(d, d, san);
                    d = a.y - nn.y + EPSV; san = fmaf(d, d, san);
                    d = a.z - nn.z + EPSV; san = fmaf(d, d, san);
                    d = a.w - nn.w + EPSV; san = fmaf(d, d, san);
                    a = a2; pp = p2; nn = n2;
                }
            } else {
                int nv = D >> 2;
                for (int k = lane; k < nv; k += 32) {
                    float4 av = A[k], pp = P[k], nn = N[k];
                    float d;
                    d = av.x - pp.x + EPSV; sap = fmaf(d, d, sap);
                    d = av.y - pp.y + EPSV; sap = fmaf(d, d, sap);
                    d = av.z - pp.z + EPSV; sap = fmaf(d, d, sap);
                    d = av.w - pp.w + EPSV; sap = fmaf(d, d, sap);
                    d = av.x - nn.x + EPSV; san = fmaf(d, d, san);
                    d = av.y - nn.y + EPSV; san = fmaf(d, d, san);
                    d = av.z - nn.z + EPSV; san = fmaf(d, d, san);
                    d = av.w - nn.w + EPSV; san = fmaf(d, d, san);
                }
            }
            #pragma unroll
            for (int off = 16; off > 0; off >>= 1) {
                sap += __shfl_down_sync(0xffffffffu, sap, off);
                san += __shfl_down_sync(0xffffffffu, san, off);
            }
            my_loss = fmaxf(sqrtf(sap) - sqrtf(san) + MARGIN, 0.0f);
            my_val  = 1;
        }
    }

    // block-partial reduction (fixed order -> deterministic)
    if (lane == 0) { s_loss[wib] = my_loss; s_val[wib] = my_val; }
    __syncthreads();
    if (threadIdx.x == 0) {
        float sum = 0.0f; int cnt = 0;
        #pragma unroll
        for (int j = 0; j < 16; j++) { sum += s_loss[j]; cnt += s_val[j]; }
        g_part[blockIdx.x] = make_float2(sum, (float)cnt);
    }
}

// ================================================================ kernel C
// Deterministic single-block reduction over block partials.
__global__ void k_reduce(float* __restrict__ out, int npart) {
    __shared__ float s_sum[512];
    __shared__ float s_cnt[512];
    int t = threadIdx.x;
    float sum = 0.0f, cnt = 0.0f;
    for (int i = t; i < npart; i += blockDim.x) {
        float2 v = g_part[i];
        sum += v.x; cnt += v.y;
    }
    s_sum[t] = sum;
    s_cnt[t] = cnt;
    __syncthreads();
    for (int off = (int)blockDim.x >> 1; off > 0; off >>= 1) {
        if (t < off) {
            s_sum[t] += s_sum[t + off];
            s_cnt[t] += s_cnt[t + off];
        }
        __syncthreads();
    }
    if (t == 0)
        out[0] = (s_cnt[0] > 0.0f) ? (s_sum[0] / s_cnt[0]) : 0.0f;
}

// ================================================================ launch
extern "C" void kernel_launch(void* const* d_in, const int* in_sizes, int n_in,
                              void* d_out, int out_size) {
    int i_feat = (in_sizes[0] >= in_sizes[1]) ? 0 : 1;
    int i_lab  = 1 - i_feat;
    const float* features = (const float*)d_in[i_feat];
    const void*  labels   = d_in[i_lab];
    int B = in_sizes[i_lab];
    int D = in_sizes[i_feat] / B;

    int nblk = (B + 15) / 16;       // 16 anchors per 512-thread block (R11 shape)
    k_occ_part<<<NSLOT, 1024>>>(labels, B);
    k_dist    <<<nblk, 512>>>(features, B, D);
    k_reduce  <<<1, 512>>>((float*)d_out, nblk);
}